// round 14
// baseline (speedup 1.0000x reference)
#include <cuda_runtime.h>
#include <math.h>

#define Lq   4096
#define NFFT 8192
#define Mh   4096
#define Hh   512
#define Bb   8
#define Nn   64
#define GSTRIDE 4104

typedef unsigned long long ull;
typedef ulonglong2 u2;

__device__ float  g_K[Hh * Lq];
__device__ float2 g_G[Hh * GSTRIDE];
__device__ float2 g_tw[NFFT / 2];        // W_8192^j, j<4096
__device__ float4 g_coef[Hh * Nn];

#define PD(i) ((i) + ((i) >> 4))
#define PDN 4352

// ---------------- scalar complex helpers (twiddle chains only) ----------------
__device__ __forceinline__ float2 cmulf(float2 a, float2 b) {
    return make_float2(fmaf(a.x, b.x, -a.y * b.y), fmaf(a.x, b.y, a.y * b.x));
}

// ---------------- f32x2 packed primitives ----------------
__device__ __forceinline__ ull pk2(float lo, float hi){
    ull r; asm("mov.b64 %0,{%1,%2};":"=l"(r):"f"(lo),"f"(hi)); return r;
}
__device__ __forceinline__ void upk2(ull v, float& lo, float& hi){
    asm("mov.b64 {%0,%1},%2;":"=f"(lo),"=f"(hi):"l"(v));
}
__device__ __forceinline__ ull f2add(ull a, ull b){
    ull r; asm("add.rn.f32x2 %0,%1,%2;":"=l"(r):"l"(a),"l"(b)); return r;
}
__device__ __forceinline__ ull f2mul(ull a, ull b){
    ull r; asm("mul.rn.f32x2 %0,%1,%2;":"=l"(r):"l"(a),"l"(b)); return r;
}
__device__ __forceinline__ ull f2fma(ull a, ull b, ull c){
    ull r; asm("fma.rn.f32x2 %0,%1,%2,%3;":"=l"(r):"l"(a),"l"(b),"l"(c)); return r;
}
__device__ __forceinline__ ull f2sub(ull a, ull b){ return f2fma(b, pk2(-1.f,-1.f), a); }
__device__ __forceinline__ ull f2neg(ull a){ return f2mul(a, pk2(-1.f,-1.f)); }

// two-row packed complex: r = (reA, reB), i = (imA, imB)
struct c2 { ull r, i; };

__device__ __forceinline__ c2 ldp(const u2* p){ u2 v = *p; c2 o; o.r = v.x; o.i = v.y; return o; }
__device__ __forceinline__ void stp(u2* p, c2 v){ *p = make_ulonglong2(v.r, v.i); }

__device__ __forceinline__ c2 c2add(c2 a, c2 b){ c2 o; o.r=f2add(a.r,b.r); o.i=f2add(a.i,b.i); return o; }
__device__ __forceinline__ c2 c2sub(c2 a, c2 b){ c2 o; o.r=f2sub(a.r,b.r); o.i=f2sub(a.i,b.i); return o; }
__device__ __forceinline__ c2 c2mulw(c2 a, float2 w){
    ull wr = pk2(w.x, w.x), wi = pk2(w.y, w.y), nwi = pk2(-w.y, -w.y);
    c2 o;
    o.r = f2fma(a.r, wr, f2mul(a.i, nwi));
    o.i = f2fma(a.r, wi, f2mul(a.i, wr));
    return o;
}
__device__ __forceinline__ c2 c2mulni(c2 a){ c2 o; o.r = a.i; o.i = f2neg(a.r); return o; }

// ---------------- packed DFT4s ----------------
#define DFT4P(p0,p1,p2,p3,q0,q1,q2,q3) { \
    c2 t0=c2add(p0,p2), t1=c2sub(p0,p2), t2=c2add(p1,p3), t3=c2sub(p1,p3); \
    q0=c2add(t0,t2); q2=c2sub(t0,t2); \
    q1.r=f2add(t1.r,t3.i); q1.i=f2sub(t1.i,t3.r); \
    q3.r=f2sub(t1.r,t3.i); q3.i=f2add(t1.i,t3.r); }

#define DFT4HP(p0,p1,q0,q1,q2,q3) { \
    q0=c2add(p0,p1); q2=c2sub(p0,p1); \
    q1.r=f2add(p0.r,p1.i); q1.i=f2sub(p0.i,p1.r); \
    q3.r=f2sub(p0.r,p1.i); q3.i=f2add(p0.i,p1.r); }

#define DFT4_01P(p0,p1,p2,p3,q0,q1) { \
    c2 t0=c2add(p0,p2), t1=c2sub(p0,p2), t2=c2add(p1,p3), t3=c2sub(p1,p3); \
    q0=c2add(t0,t2); \
    q1.r=f2add(t1.r,t3.i); q1.i=f2sub(t1.i,t3.r); }

#define W16_1 make_float2( 0.9238795325112867f, -0.3826834323650898f)
#define W16_2 make_float2( 0.7071067811865476f, -0.7071067811865476f)
#define W16_3 make_float2( 0.3826834323650898f, -0.9238795325112867f)
#define W16_6 make_float2(-0.7071067811865476f, -0.7071067811865476f)
#define W16_9 make_float2(-0.9238795325112867f,  0.3826834323650898f)

#define ALAYERP(x,A0,A1,A2,A3) { \
    DFT4P(x[0],x[4],x[8],x[12], A0[0],A0[1],A0[2],A0[3]); \
    DFT4P(x[1],x[5],x[9],x[13], A1[0],A1[1],A1[2],A1[3]); \
    DFT4P(x[2],x[6],x[10],x[14],A2[0],A2[1],A2[2],A2[3]); \
    DFT4P(x[3],x[7],x[11],x[15],A3[0],A3[1],A3[2],A3[3]); }

#define ALAYER_HALFP(z,A0,A1,A2,A3) { \
    DFT4HP(z[0],z[4],A0[0],A0[1],A0[2],A0[3]); \
    DFT4HP(z[1],z[5],A1[0],A1[1],A1[2],A1[3]); \
    DFT4HP(z[2],z[6],A2[0],A2[1],A2[2],A2[3]); \
    DFT4HP(z[3],z[7],A3[0],A3[1],A3[2],A3[3]); }

#define BLAYER_TWP(A0,A1,A2,A3,y,W1IN) { \
    float2 w1=(W1IN); \
    float2 w2=cmulf(w1,w1), w3=cmulf(w2,w1), w4=cmulf(w2,w2); \
    float2 w8=cmulf(w4,w4), w12=cmulf(w8,w4); \
    DFT4P(A0[0],A1[0],A2[0],A3[0], y[0],y[4],y[8],y[12]); \
    { c2 v0=c2mulw(A0[1],w1); \
      c2 v1=c2mulw(A1[1],cmulf(W16_1,w1)); \
      c2 v2=c2mulw(A2[1],cmulf(W16_2,w1)); \
      c2 v3=c2mulw(A3[1],cmulf(W16_3,w1)); \
      DFT4P(v0,v1,v2,v3, y[1],y[5],y[9],y[13]); } \
    { c2 v0=c2mulw(A0[2],w2); \
      c2 v1=c2mulw(A1[2],cmulf(W16_2,w2)); \
      c2 v2=c2mulw(A2[2],make_float2(w2.y,-w2.x)); \
      c2 v3=c2mulw(A3[2],cmulf(W16_6,w2)); \
      DFT4P(v0,v1,v2,v3, y[2],y[6],y[10],y[14]); } \
    { c2 v0=c2mulw(A0[3],w3); \
      c2 v1=c2mulw(A1[3],cmulf(W16_3,w3)); \
      c2 v2=c2mulw(A2[3],cmulf(W16_6,w3)); \
      c2 v3=c2mulw(A3[3],cmulf(W16_9,w3)); \
      DFT4P(v0,v1,v2,v3, y[3],y[7],y[11],y[15]); } \
    _Pragma("unroll") \
    for (int m1=0;m1<4;m1++){ \
        y[m1+4]=c2mulw(y[m1+4],w4); y[m1+8]=c2mulw(y[m1+8],w8); y[m1+12]=c2mulw(y[m1+12],w12); } }

#define BLAYER_UNITP(A0,A1,A2,A3,y) { \
    DFT4P(A0[0],A1[0],A2[0],A3[0], y[0],y[4],y[8],y[12]); \
    { c2 v1=c2mulw(A1[1],W16_1), v2=c2mulw(A2[1],W16_2), v3=c2mulw(A3[1],W16_3); \
      DFT4P(A0[1],v1,v2,v3, y[1],y[5],y[9],y[13]); } \
    { c2 v1=c2mulw(A1[2],W16_2); \
      c2 v2=c2mulni(A2[2]); \
      c2 v3=c2mulw(A3[2],W16_6); \
      DFT4P(A0[2],v1,v2,v3, y[2],y[6],y[10],y[14]); } \
    { c2 v1=c2mulw(A1[3],W16_3), v2=c2mulw(A2[3],W16_6), v3=c2mulw(A3[3],W16_9); \
      DFT4P(A0[3],v1,v2,v3, y[3],y[7],y[11],y[15]); } }

#define BLAYER_UNIT_HALFP(A0,A1,A2,A3,y) { \
    DFT4_01P(A0[0],A1[0],A2[0],A3[0], y[0],y[4]); \
    { c2 v1=c2mulw(A1[1],W16_1), v2=c2mulw(A2[1],W16_2), v3=c2mulw(A3[1],W16_3); \
      DFT4_01P(A0[1],v1,v2,v3, y[1],y[5]); } \
    { c2 v1=c2mulw(A1[2],W16_2); \
      c2 v2=c2mulni(A2[2]); \
      c2 v3=c2mulw(A3[2],W16_6); \
      DFT4_01P(A0[2],v1,v2,v3, y[2],y[6]); } \
    { c2 v1=c2mulw(A1[3],W16_3), v2=c2mulw(A2[3],W16_6), v3=c2mulw(A3[3],W16_9); \
      DFT4_01P(A0[3],v1,v2,v3, y[3],y[7]); } }

// ---------------- setup: twiddles (blocks 0..15) + coeffs (blocks 16..527) --------
__global__ void setup_kernel(const float* __restrict__ W,
                             const float* __restrict__ log_step,
                             const float* __restrict__ Lre,
                             const float* __restrict__ Lim) {
    if (blockIdx.x < 16) {
        int j = blockIdx.x * 256 + threadIdx.x;
        if (j < NFFT / 2) {
            float s, c;
            sincospif(-(float)j * (1.0f / 4096.0f), &s, &c);
            g_tw[j] = make_float2(c, s);
        }
        return;
    }
    int h = blockIdx.x - 16;
    int n = threadIdx.x;
    if (n >= Nn) return;
    float step = expf(log_step[h]);
    float Lr = Lre[n], Li = Lim[n];
    float qr = step * Lr, qi = step * Li;

    double sgn = (qr > 0.f) ? -1.0 : 1.0;
    double pr = sgn * (double)qr, pi = sgn * (double)qi;

    double eL = exp(pr * (double)Lq);
    double sL, cL;
    sincos(pi * (double)Lq, &sL, &cL);
    double num_re = eL * cL - 1.0;
    double num_im = eL * sL;

    double sp, cp;
    sincos(pi, &sp, &cp);
    double em1 = expm1(pr);
    double hs  = sin(0.5 * pi);
    double den_re = em1 * cp - 2.0 * hs * hs;
    double den_im = (em1 + 1.0) * sp;
    double dmag = den_re * den_re + den_im * den_im;

    double s_re, s_im;
    if (dmag > 0.0) {
        s_re = (num_re * den_re + num_im * den_im) / dmag;
        s_im = (num_im * den_re - num_re * den_im) / dmag;
    } else {
        s_re = (double)Lq;
        s_im = 0.0;
    }

    double w0 = W[(h * Nn + n) * 2 + 0];
    double w1 = W[(h * Nn + n) * 2 + 1];
    double lmag = (double)Lr * Lr + (double)Li * Li;
    double a_re = (w0 * Lr + w1 * Li) / lmag;
    double a_im = (w1 * Lr - w0 * Li) / lmag;
    double smag = s_re * s_re + s_im * s_im + 1e-7;
    double b_re =  s_re / smag;
    double b_im = -s_im / smag;
    float cr = (float)(a_re * b_re - a_im * b_im);
    float ci = (float)(a_re * b_im + a_im * b_re);
    g_coef[h * Nn + n] = make_float4(qr, qi, cr, ci);
}

// ---------------- K: packed recurrence, coeff folded into anchor ----------------
__global__ __launch_bounds__(256) void k_kernel() {
    extern __shared__ float kbuf[];     // 8 * 2048 floats = 64KB
    int blk  = blockIdx.x;
    int h    = blk >> 1;
    int half = blk & 1;
    int tid  = threadIdx.x;
    int cp   = tid & 31;
    int g    = tid >> 5;
    int l0a  = (half * 32 + cp) * 32;
    int l0b  = l0a + 2048;

    ull acc[32];
#pragma unroll
    for (int j = 0; j < 32; j++) acc[j] = 0ULL;

    for (int nn = 0; nn < 8; nn++) {
        int n = (g << 3) + nn;
        float4 cf = g_coef[h * Nn + n];
        float qr = cf.x, qi = cf.y, cr = cf.z, ci = cf.w;
        bool fwd = (qr <= 0.f);

        float ara, aia, arb, aib, lrS, liS;
        if (fwd) {
            float d0a = (float)l0a, d0b = (float)l0b;
            float ma = expf(qr * d0a), mb = expf(qr * d0b);
            float sa, ca2, sb, cb2;
            sincosf(qi * d0a, &sa, &ca2);
            sincosf(qi * d0b, &sb, &cb2);
            ara = ma * ca2; aia = ma * sa;
            arb = mb * cb2; aib = mb * sb;
            float em = expf(qr);
            float sl, cl2; sincosf(qi, &sl, &cl2);
            lrS = em * cl2; liS = em * sl;
        } else {
            float d0a = (float)(l0a + 31 - (Lq - 1));
            float d0b = (float)(l0b + 31 - (Lq - 1));
            float ma = expf(qr * d0a), mb = expf(qr * d0b);
            float sa, ca2, sb, cb2;
            sincosf(qi * d0a, &sa, &ca2);
            sincosf(qi * d0b, &sb, &cb2);
            ara = ma * ca2; aia = ma * sa;
            arb = mb * cb2; aib = mb * sb;
            float em = expf(-qr);
            float sl, cl2; sincosf(-qi, &sl, &cl2);
            lrS = em * cl2; liS = em * sl;
        }

        ull ar2 = pk2(ara, arb), ai2 = pk2(aia, aib);
        ull lr2 = pk2(lrS, lrS), li2 = pk2(liS, liS);
        ull nli2 = pk2(-liS, -liS);
        ull cr2 = pk2(cr, cr), ci2 = pk2(ci, ci), nci2 = pk2(-ci, -ci);

        {
            ull par = f2fma(cr2, ar2, f2mul(nci2, ai2));
            ull pai = f2fma(cr2, ai2, f2mul(ci2, ar2));
            ar2 = par; ai2 = pai;
        }

        if (fwd) {
#pragma unroll
            for (int j = 0; j < 32; j++) {
                acc[j] = f2add(acc[j], ar2);
                ull t = f2fma(ar2, lr2, f2mul(ai2, nli2));
                ai2 = f2fma(ar2, li2, f2mul(ai2, lr2));
                ar2 = t;
            }
        } else {
#pragma unroll
            for (int j = 31; j >= 0; j--) {
                acc[j] = f2add(acc[j], ar2);
                ull t = f2fma(ar2, lr2, f2mul(ai2, nli2));
                ai2 = f2fma(ar2, li2, f2mul(ai2, lr2));
                ar2 = t;
            }
        }
    }

#pragma unroll
    for (int j = 0; j < 32; j++) {
        float a, b; upk2(acc[j], a, b);
        kbuf[g * 2048 + (cp << 5) + j]        = a;
        kbuf[g * 2048 + 1024 + (cp << 5) + j] = b;
    }
    __syncthreads();
    for (int i = tid; i < 2048; i += 256) {
        float s = 0.f;
#pragma unroll
        for (int gg = 0; gg < 8; gg++) s += kbuf[gg * 2048 + i];
        int l = (i < 1024) ? (half * 1024 + i) : (2048 + half * 1024 + (i - 1024));
        g_K[h * Lq + l] = s;
    }
}

// ---------------- packed FFT stages --------------------------------------------
// Index identities (carry-free splits, verified):
//   PD(tid + 256r)        = PD(tid) + 272r
//   PD(16*tid + m)        = 17*tid + m           (m < 16)
//   PD(16*pp + q + 16m)   = q + 17*pp + 17m      (q < 16)
//   PD(4096 - tid - 256r) = PD(4096 - tid) - 272r
__device__ __forceinline__ void fft_stage0_regsP(u2* X, int tid, const c2 z[8]) {
    c2 A0[4], A1[4], A2[4], A3[4];
    ALAYER_HALFP(z, A0, A1, A2, A3);
    c2 y[16];
    BLAYER_TWP(A0, A1, A2, A3, y, g_tw[tid << 1]);
    u2* Wp = X + 17 * tid;
#pragma unroll
    for (int m = 0; m < 16; m++) stp(Wp + m, y[m]);
    __syncthreads();
}

__device__ __forceinline__ void fft_stage1P(u2* X, int tid) {
    int q = tid & 15, pp = tid - q;
    const u2* Rp = X + PD(tid);
    c2 x[16];
#pragma unroll
    for (int r = 0; r < 16; r++) x[r] = ldp(Rp + 272 * r);
    __syncthreads();
    c2 A0[4], A1[4], A2[4], A3[4];
    ALAYERP(x, A0, A1, A2, A3);
    c2 y[16];
    BLAYER_TWP(A0, A1, A2, A3, y, g_tw[pp << 1]);
    u2* Wp = X + q + 17 * pp;
#pragma unroll
    for (int m = 0; m < 16; m++) stp(Wp + 17 * m, y[m]);
    __syncthreads();
}

// forward stage2: keep ALL outputs in regs; store only UPPER half (m>=8) to smem.
__device__ __forceinline__ void fft_stage2_keepP(u2* X, int tid, c2 y[16]) {
    u2* Bp = X + PD(tid);
    c2 x[16];
#pragma unroll
    for (int r = 0; r < 16; r++) x[r] = ldp(Bp + 272 * r);
    c2 A0[4], A1[4], A2[4], A3[4];
    ALAYERP(x, A0, A1, A2, A3);
    BLAYER_UNITP(A0, A1, A2, A3, y);
#pragma unroll
    for (int m = 8; m < 16; m++) stp(Bp + 272 * m, y[m]);
    __syncthreads();
}

// inverse stage0: lower 8 inputs from regs (kept S), upper 8 from smem
__device__ __forceinline__ void fft_stage0_mixedP(u2* X, int tid, const c2 S[8]) {
    const u2* Bp = X + PD(tid);
    c2 x[16];
#pragma unroll
    for (int m = 8; m < 16; m++) x[m] = ldp(Bp + 272 * m);
#pragma unroll
    for (int m = 0; m < 8; m++) x[m] = S[m];
    __syncthreads();
    c2 A0[4], A1[4], A2[4], A3[4];
    ALAYERP(x, A0, A1, A2, A3);
    c2 y[16];
    BLAYER_TWP(A0, A1, A2, A3, y, g_tw[tid << 1]);
    u2* Wp = X + 17 * tid;
#pragma unroll
    for (int m = 0; m < 16; m++) stp(Wp + m, y[m]);
    __syncthreads();
}

// ---------------- rfft8192(K) -> G, two h-rows per block ----------------
__global__ __launch_bounds__(256, 2) void fftG_kernel() {
    extern __shared__ u2 smu[];
    u2* X = smu;
    int h0 = blockIdx.x, h1 = h0 + 256;
    int tid = threadIdx.x;
    const float2* kA = (const float2*)(g_K + (size_t)h0 * Lq);
    const float2* kB = (const float2*)(g_K + (size_t)h1 * Lq);
    {
        c2 z[8];
#pragma unroll
        for (int r = 0; r < 8; r++) {
            float2 a = kA[tid + (r << 8)], b = kB[tid + (r << 8)];
            z[r].r = pk2(a.x, b.x);
            z[r].i = pk2(a.y, b.y);
        }
        fft_stage0_regsP(X, tid, z);
    }
    fft_stage1P(X, tid);
    c2 y[16];
    fft_stage2_keepP(X, tid, y);     // lower half kept in y[0..7], upper in smem

    float2* G0 = g_G + (size_t)h0 * GSTRIDE;
    float2* G1 = g_G + (size_t)h1 * GSTRIDE;
    const u2* Pp = X + PD(4096 - tid);   // partner base: index - 272r
#pragma unroll
    for (int r = 0; r < 8; r++) {
        int k = tid + (r << 8);
        if (k == 0) {
            c2 z0 = y[0];
            ull s = f2add(z0.r, z0.i);
            ull d = f2sub(z0.r, z0.i);
            float sa, sb, da, db; upk2(s, sa, sb); upk2(d, da, db);
            G0[0] = make_float2(sa, 0.f);    G1[0] = make_float2(sb, 0.f);
            G0[4096] = make_float2(da, 0.f); G1[4096] = make_float2(db, 0.f);
            c2 z2 = y[8]; z2.i = f2neg(z2.i);
            float ra, rb, ia, ib; upk2(z2.r, ra, rb); upk2(z2.i, ia, ib);
            G0[2048] = make_float2(ra, ia);  G1[2048] = make_float2(rb, ib);
        } else {
            c2 zk = y[r];
            c2 zm = ldp(Pp - 272 * r);
            ull half = pk2(0.5f, 0.5f), nhalf = pk2(-0.5f, -0.5f);
            c2 xe, xo;
            xe.r = f2mul(f2add(zk.r, zm.r), half);
            xe.i = f2mul(f2sub(zk.i, zm.i), half);
            xo.r = f2mul(f2add(zk.i, zm.i), half);
            xo.i = f2mul(f2sub(zk.r, zm.r), nhalf);
            float2 w = g_tw[k];
            c2 wxo = c2mulw(xo, w);
            c2 gf, gb;
            gf.r = f2add(xe.r, wxo.r); gf.i = f2add(xe.i, wxo.i);
            gb.r = f2sub(xe.r, wxo.r); gb.i = f2neg(f2sub(xe.i, wxo.i));
            float ra, rb, ia, ib;
            upk2(gf.r, ra, rb); upk2(gf.i, ia, ib);
            G0[k] = make_float2(ra, ia); G1[k] = make_float2(rb, ib);
            upk2(gb.r, ra, rb); upk2(gb.i, ia, ib);
            G0[4096 - k] = make_float2(ra, ia); G1[4096 - k] = make_float2(rb, ib);
        }
    }
}

// ---------------- conv: two (b,h) rows per block, fully f32x2 packed --------------
__global__ __launch_bounds__(256, 2) void conv_kernel(const float* __restrict__ u,
                                                      const float* __restrict__ D,
                                                      float* __restrict__ out) {
    extern __shared__ u2 smu[];
    u2* X = smu;
    int blk = blockIdx.x;                 // 0..2047
    int h   = blk & (Hh - 1);
    int bp  = blk >> 9;                   // 0..3
    size_t rowA = (size_t)(2 * bp) * Hh + h;
    size_t rowB = rowA + Hh;
    int tid = threadIdx.x;
    const float2* uA = (const float2*)(u + rowA * Lq);
    const float2* uB = (const float2*)(u + rowB * Lq);

    c2 ur[8];
#pragma unroll
    for (int r = 0; r < 8; r++) {
        float2 a = uA[tid + (r << 8)], b = uB[tid + (r << 8)];
        ur[r].r = pk2(a.x, b.x);
        ur[r].i = pk2(a.y, b.y);
    }

    // forward FFT (packed real input, upper half zero)
    fft_stage0_regsP(X, tid, ur);
    fft_stage1P(X, tid);
    c2 y[16];
    fft_stage2_keepP(X, tid, y);     // lower kept in y[0..7], upper in smem (+regs)

    // middle: prefetch G (L2), read upper partners from smem, sync, compute.
    const float2* G = g_G + (size_t)h * GSTRIDE;
    float2 gk[8], gm[8];
#pragma unroll
    for (int r = 0; r < 8; r++) {
        int k = tid + (r << 8);
        if (k == 0) { gk[0] = G[0]; gm[0] = G[4096]; }
        else        { gk[r] = G[k]; gm[r] = G[4096 - k]; }
    }
    float2 g2048; if (tid == 0) g2048 = G[2048];

    u2* Pp = X + PD(4096 - tid);         // partner base: index - 272r
    c2 sb[8];
#pragma unroll
    for (int r = 0; r < 8; r++) {
        int k = tid + (r << 8);
        if (k == 0) { sb[r].r = 0ULL; sb[r].i = 0ULL; }
        else        { sb[r] = ldp(Pp - 272 * r); }
    }
    __syncthreads();

    c2 S[8];                          // kept lower outputs (conj-stored ifft inputs)
#pragma unroll
    for (int r = 0; r < 8; r++) {
        int k = tid + (r << 8);
        ull half = pk2(0.5f, 0.5f), nhalf = pk2(-0.5f, -0.5f);
        if (k == 0) {
            c2 z0 = y[0];
            ull x0 = f2add(z0.r, z0.i);
            ull xM = f2sub(z0.r, z0.i);
            ull y0 = f2mul(x0, pk2(gk[0].x, gk[0].x));
            ull yM = f2mul(xM, pk2(gm[0].x, gm[0].x));
            S[0].r = f2mul(f2add(y0, yM), half);
            S[0].i = f2mul(f2sub(y0, yM), nhalf);
            c2 t; t.r = y[8].r; t.i = f2neg(y[8].i);     // Z[2048] = own y[8]
            stp(X + 2176, c2mulw(t, g2048));             // PD(2048) = 2176
        } else {
            c2 zk = y[r], zm = sb[r];
            c2 xe, xo;
            xe.r = f2mul(f2add(zk.r, zm.r), half);
            xe.i = f2mul(f2sub(zk.i, zm.i), half);
            xo.r = f2mul(f2add(zk.i, zm.i), half);
            xo.i = f2mul(f2sub(zk.r, zm.r), nhalf);
            float2 w = g_tw[k];
            c2 wxo = c2mulw(xo, w);
            c2 xf, xb;
            xf.r = f2add(xe.r, wxo.r); xf.i = f2add(xe.i, wxo.i);
            xb.r = f2sub(xe.r, wxo.r); xb.i = f2neg(f2sub(xe.i, wxo.i));
            c2 ya = c2mulw(xf, gk[r]);
            c2 yb = c2mulw(xb, gm[r]);
            c2 ye, dd;
            ye.r = f2mul(f2add(ya.r, yb.r), half);
            ye.i = f2mul(f2sub(ya.i, yb.i), half);
            dd.r = f2sub(ya.r, yb.r);
            dd.i = f2add(ya.i, yb.i);
            c2 yo = c2mulw(dd, make_float2(w.x, -w.y));
            yo.r = f2mul(yo.r, half); yo.i = f2mul(yo.i, half);
            // conj-stored outputs
            S[r].r = f2sub(ye.r, yo.i);
            S[r].i = f2neg(f2add(ye.i, yo.r));
            c2 ob2;
            ob2.r = f2add(ye.r, yo.i);
            ob2.i = f2sub(ye.i, yo.r);
            stp(Pp - 272 * r, ob2);
        }
    }
    __syncthreads();

    // inverse FFT: stage0 mixed (lower from regs, upper from smem)
    fft_stage0_mixedP(X, tid, S);
    fft_stage1P(X, tid);
    {
        const u2* Bp = X + PD(tid);
        c2 x[16];
#pragma unroll
        for (int r = 0; r < 16; r++) x[r] = ldp(Bp + 272 * r);
        c2 A0[4], A1[4], A2[4], A3[4];
        ALAYERP(x, A0, A1, A2, A3);
        c2 yf[8];
        BLAYER_UNIT_HALFP(A0, A1, A2, A3, yf);

        float dh = D[h];
        ull dh2 = pk2(dh, dh);
        ull inv2 = pk2(1.0f / Mh, 1.0f / Mh);
        ull ninv2 = pk2(-1.0f / Mh, -1.0f / Mh);
        float2* oA = (float2*)(out + rowA * Lq);
        float2* oB = (float2*)(out + rowB * Lq);
#pragma unroll
        for (int m = 0; m < 8; m++) {
            ull resr = f2fma(ur[m].r, dh2, f2mul(yf[m].r, inv2));
            ull resi = f2fma(ur[m].i, dh2, f2mul(yf[m].i, ninv2));
            float ra, rb, ia, ib;
            upk2(resr, ra, rb); upk2(resi, ia, ib);
            oA[tid + (m << 8)] = make_float2(ra, ia);
            oB[tid + (m << 8)] = make_float2(rb, ib);
        }
    }
}

// ---------------- launcher ----------------
extern "C" void kernel_launch(void* const* d_in, const int* in_sizes, int n_in,
                              void* d_out, int out_size) {
    const float* u  = (const float*)d_in[0];
    const float* W  = (const float*)d_in[1];
    const float* D  = (const float*)d_in[2];
    const float* ls = (const float*)d_in[3];
    const float* Lr = (const float*)d_in[4];
    const float* Li = (const float*)d_in[5];
    float* out = (float*)d_out;

    int fft_smem = PDN * (int)sizeof(u2);             // 69632 B
    int k_smem   = 8 * 2048 * (int)sizeof(float);     // 65536 B

    cudaFuncSetAttribute(k_kernel,    cudaFuncAttributeMaxDynamicSharedMemorySize, k_smem);
    cudaFuncSetAttribute(fftG_kernel, cudaFuncAttributeMaxDynamicSharedMemorySize, fft_smem);
    cudaFuncSetAttribute(conv_kernel, cudaFuncAttributeMaxDynamicSharedMemorySize, fft_smem);

    setup_kernel<<<16 + Hh, 256>>>(W, ls, Lr, Li);
    k_kernel<<<2 * Hh, 256, k_smem>>>();
    fftG_kernel<<<Hh / 2, 256, fft_smem>>>();
    conv_kernel<<<Bb * Hh / 2, 256, fft_smem>>>(u, D, out);
}

// round 16
// speedup vs baseline: 1.0193x; 1.0193x over previous
#include <cuda_runtime.h>
#include <math.h>

#define Lq   4096
#define NFFT 8192
#define Mh   4096
#define Hh   512
#define Bb   8
#define Nn   64
#define GSTRIDE 4104

typedef unsigned long long ull;
typedef ulonglong2 u2;

__device__ float  g_K[Hh * Lq];
__device__ float2 g_G[Hh * GSTRIDE];
__device__ float2 g_tw[NFFT / 2];        // W_8192^j, j<4096
__device__ float4 g_coef[Hh * Nn];

#define PD(i) ((i) + ((i) >> 4))
#define PDN 4352

// ---------------- scalar complex helpers (twiddle chains only) ----------------
__device__ __forceinline__ float2 cmulf(float2 a, float2 b) {
    return make_float2(fmaf(a.x, b.x, -a.y * b.y), fmaf(a.x, b.y, a.y * b.x));
}

// ---------------- f32x2 packed primitives ----------------
__device__ __forceinline__ ull pk2(float lo, float hi){
    ull r; asm("mov.b64 %0,{%1,%2};":"=l"(r):"f"(lo),"f"(hi)); return r;
}
__device__ __forceinline__ void upk2(ull v, float& lo, float& hi){
    asm("mov.b64 {%0,%1},%2;":"=f"(lo),"=f"(hi):"l"(v));
}
__device__ __forceinline__ ull f2add(ull a, ull b){
    ull r; asm("add.rn.f32x2 %0,%1,%2;":"=l"(r):"l"(a),"l"(b)); return r;
}
__device__ __forceinline__ ull f2mul(ull a, ull b){
    ull r; asm("mul.rn.f32x2 %0,%1,%2;":"=l"(r):"l"(a),"l"(b)); return r;
}
__device__ __forceinline__ ull f2fma(ull a, ull b, ull c){
    ull r; asm("fma.rn.f32x2 %0,%1,%2,%3;":"=l"(r):"l"(a),"l"(b),"l"(c)); return r;
}
__device__ __forceinline__ ull f2sub(ull a, ull b){ return f2fma(b, pk2(-1.f,-1.f), a); }
__device__ __forceinline__ ull f2neg(ull a){ return f2mul(a, pk2(-1.f,-1.f)); }

// two-row packed complex: r = (reA, reB), i = (imA, imB)
struct c2 { ull r, i; };

__device__ __forceinline__ c2 ldc(const u2* X, int idx){ u2 v = X[idx]; c2 o; o.r = v.x; o.i = v.y; return o; }
__device__ __forceinline__ void stc(u2* X, int idx, c2 v){ X[idx] = make_ulonglong2(v.r, v.i); }

__device__ __forceinline__ c2 c2add(c2 a, c2 b){ c2 o; o.r=f2add(a.r,b.r); o.i=f2add(a.i,b.i); return o; }
__device__ __forceinline__ c2 c2sub(c2 a, c2 b){ c2 o; o.r=f2sub(a.r,b.r); o.i=f2sub(a.i,b.i); return o; }
__device__ __forceinline__ c2 c2mulw(c2 a, float2 w){
    ull wr = pk2(w.x, w.x), wi = pk2(w.y, w.y), nwi = pk2(-w.y, -w.y);
    c2 o;
    o.r = f2fma(a.r, wr, f2mul(a.i, nwi));
    o.i = f2fma(a.r, wi, f2mul(a.i, wr));
    return o;
}
__device__ __forceinline__ c2 c2mulni(c2 a){ c2 o; o.r = a.i; o.i = f2neg(a.r); return o; }

// ---------------- packed DFT4s ----------------
#define DFT4P(p0,p1,p2,p3,q0,q1,q2,q3) { \
    c2 t0=c2add(p0,p2), t1=c2sub(p0,p2), t2=c2add(p1,p3), t3=c2sub(p1,p3); \
    q0=c2add(t0,t2); q2=c2sub(t0,t2); \
    q1.r=f2add(t1.r,t3.i); q1.i=f2sub(t1.i,t3.r); \
    q3.r=f2sub(t1.r,t3.i); q3.i=f2add(t1.i,t3.r); }

#define DFT4HP(p0,p1,q0,q1,q2,q3) { \
    q0=c2add(p0,p1); q2=c2sub(p0,p1); \
    q1.r=f2add(p0.r,p1.i); q1.i=f2sub(p0.i,p1.r); \
    q3.r=f2sub(p0.r,p1.i); q3.i=f2add(p0.i,p1.r); }

#define DFT4_01P(p0,p1,p2,p3,q0,q1) { \
    c2 t0=c2add(p0,p2), t1=c2sub(p0,p2), t2=c2add(p1,p3), t3=c2sub(p1,p3); \
    q0=c2add(t0,t2); \
    q1.r=f2add(t1.r,t3.i); q1.i=f2sub(t1.i,t3.r); }

#define W16_1 make_float2( 0.9238795325112867f, -0.3826834323650898f)
#define W16_2 make_float2( 0.7071067811865476f, -0.7071067811865476f)
#define W16_3 make_float2( 0.3826834323650898f, -0.9238795325112867f)
#define W16_6 make_float2(-0.7071067811865476f, -0.7071067811865476f)
#define W16_9 make_float2(-0.9238795325112867f,  0.3826834323650898f)

#define ALAYERP(x,A0,A1,A2,A3) { \
    DFT4P(x[0],x[4],x[8],x[12], A0[0],A0[1],A0[2],A0[3]); \
    DFT4P(x[1],x[5],x[9],x[13], A1[0],A1[1],A1[2],A1[3]); \
    DFT4P(x[2],x[6],x[10],x[14],A2[0],A2[1],A2[2],A2[3]); \
    DFT4P(x[3],x[7],x[11],x[15],A3[0],A3[1],A3[2],A3[3]); }

#define ALAYER_HALFP(z,A0,A1,A2,A3) { \
    DFT4HP(z[0],z[4],A0[0],A0[1],A0[2],A0[3]); \
    DFT4HP(z[1],z[5],A1[0],A1[1],A1[2],A1[3]); \
    DFT4HP(z[2],z[6],A2[0],A2[1],A2[2],A2[3]); \
    DFT4HP(z[3],z[7],A3[0],A3[1],A3[2],A3[3]); }

#define BLAYER_TWP(A0,A1,A2,A3,y,W1IN) { \
    float2 w1=(W1IN); \
    float2 w2=cmulf(w1,w1), w3=cmulf(w2,w1), w4=cmulf(w2,w2); \
    float2 w8=cmulf(w4,w4), w12=cmulf(w8,w4); \
    DFT4P(A0[0],A1[0],A2[0],A3[0], y[0],y[4],y[8],y[12]); \
    { c2 v0=c2mulw(A0[1],w1); \
      c2 v1=c2mulw(A1[1],cmulf(W16_1,w1)); \
      c2 v2=c2mulw(A2[1],cmulf(W16_2,w1)); \
      c2 v3=c2mulw(A3[1],cmulf(W16_3,w1)); \
      DFT4P(v0,v1,v2,v3, y[1],y[5],y[9],y[13]); } \
    { c2 v0=c2mulw(A0[2],w2); \
      c2 v1=c2mulw(A1[2],cmulf(W16_2,w2)); \
      c2 v2=c2mulw(A2[2],make_float2(w2.y,-w2.x)); \
      c2 v3=c2mulw(A3[2],cmulf(W16_6,w2)); \
      DFT4P(v0,v1,v2,v3, y[2],y[6],y[10],y[14]); } \
    { c2 v0=c2mulw(A0[3],w3); \
      c2 v1=c2mulw(A1[3],cmulf(W16_3,w3)); \
      c2 v2=c2mulw(A2[3],cmulf(W16_6,w3)); \
      c2 v3=c2mulw(A3[3],cmulf(W16_9,w3)); \
      DFT4P(v0,v1,v2,v3, y[3],y[7],y[11],y[15]); } \
    _Pragma("unroll") \
    for (int m1=0;m1<4;m1++){ \
        y[m1+4]=c2mulw(y[m1+4],w4); y[m1+8]=c2mulw(y[m1+8],w8); y[m1+12]=c2mulw(y[m1+12],w12); } }

#define BLAYER_UNITP(A0,A1,A2,A3,y) { \
    DFT4P(A0[0],A1[0],A2[0],A3[0], y[0],y[4],y[8],y[12]); \
    { c2 v1=c2mulw(A1[1],W16_1), v2=c2mulw(A2[1],W16_2), v3=c2mulw(A3[1],W16_3); \
      DFT4P(A0[1],v1,v2,v3, y[1],y[5],y[9],y[13]); } \
    { c2 v1=c2mulw(A1[2],W16_2); \
      c2 v2=c2mulni(A2[2]); \
      c2 v3=c2mulw(A3[2],W16_6); \
      DFT4P(A0[2],v1,v2,v3, y[2],y[6],y[10],y[14]); } \
    { c2 v1=c2mulw(A1[3],W16_3), v2=c2mulw(A2[3],W16_6), v3=c2mulw(A3[3],W16_9); \
      DFT4P(A0[3],v1,v2,v3, y[3],y[7],y[11],y[15]); } }

#define BLAYER_UNIT_HALFP(A0,A1,A2,A3,y) { \
    DFT4_01P(A0[0],A1[0],A2[0],A3[0], y[0],y[4]); \
    { c2 v1=c2mulw(A1[1],W16_1), v2=c2mulw(A2[1],W16_2), v3=c2mulw(A3[1],W16_3); \
      DFT4_01P(A0[1],v1,v2,v3, y[1],y[5]); } \
    { c2 v1=c2mulw(A1[2],W16_2); \
      c2 v2=c2mulni(A2[2]); \
      c2 v3=c2mulw(A3[2],W16_6); \
      DFT4_01P(A0[2],v1,v2,v3, y[2],y[6]); } \
    { c2 v1=c2mulw(A1[3],W16_3), v2=c2mulw(A2[3],W16_6), v3=c2mulw(A3[3],W16_9); \
      DFT4_01P(A0[3],v1,v2,v3, y[3],y[7]); } }

// ---------------- setup: twiddles (blocks 0..15) + coeffs (blocks 16..527) --------
__global__ void setup_kernel(const float* __restrict__ W,
                             const float* __restrict__ log_step,
                             const float* __restrict__ Lre,
                             const float* __restrict__ Lim) {
    if (blockIdx.x < 16) {
        int j = blockIdx.x * 256 + threadIdx.x;
        if (j < NFFT / 2) {
            float s, c;
            sincospif(-(float)j * (1.0f / 4096.0f), &s, &c);
            g_tw[j] = make_float2(c, s);
        }
        return;
    }
    int h = blockIdx.x - 16;
    int n = threadIdx.x;
    if (n >= Nn) return;
    float step = expf(log_step[h]);
    float Lr = Lre[n], Li = Lim[n];
    float qr = step * Lr, qi = step * Li;

    double sgn = (qr > 0.f) ? -1.0 : 1.0;
    double pr = sgn * (double)qr, pi = sgn * (double)qi;

    double eL = exp(pr * (double)Lq);
    double sL, cL;
    sincos(pi * (double)Lq, &sL, &cL);
    double num_re = eL * cL - 1.0;
    double num_im = eL * sL;

    double sp, cp;
    sincos(pi, &sp, &cp);
    double em1 = expm1(pr);
    double hs  = sin(0.5 * pi);
    double den_re = em1 * cp - 2.0 * hs * hs;
    double den_im = (em1 + 1.0) * sp;
    double dmag = den_re * den_re + den_im * den_im;

    double s_re, s_im;
    if (dmag > 0.0) {
        s_re = (num_re * den_re + num_im * den_im) / dmag;
        s_im = (num_im * den_re - num_re * den_im) / dmag;
    } else {
        s_re = (double)Lq;
        s_im = 0.0;
    }

    double w0 = W[(h * Nn + n) * 2 + 0];
    double w1 = W[(h * Nn + n) * 2 + 1];
    double lmag = (double)Lr * Lr + (double)Li * Li;
    double a_re = (w0 * Lr + w1 * Li) / lmag;
    double a_im = (w1 * Lr - w0 * Li) / lmag;
    double smag = s_re * s_re + s_im * s_im + 1e-7;
    double b_re =  s_re / smag;
    double b_im = -s_im / smag;
    float cr = (float)(a_re * b_re - a_im * b_im);
    float ci = (float)(a_re * b_im + a_im * b_re);
    g_coef[h * Nn + n] = make_float4(qr, qi, cr, ci);
}

// ---------------- K: packed recurrence, coeff folded into anchor ----------------
__global__ __launch_bounds__(256) void k_kernel() {
    extern __shared__ float kbuf[];     // 8 * 2048 floats = 64KB
    int blk  = blockIdx.x;
    int h    = blk >> 1;
    int half = blk & 1;
    int tid  = threadIdx.x;
    int cp   = tid & 31;
    int g    = tid >> 5;
    int l0a  = (half * 32 + cp) * 32;
    int l0b  = l0a + 2048;

    ull acc[32];
#pragma unroll
    for (int j = 0; j < 32; j++) acc[j] = 0ULL;

    for (int nn = 0; nn < 8; nn++) {
        int n = (g << 3) + nn;
        float4 cf = g_coef[h * Nn + n];
        float qr = cf.x, qi = cf.y, cr = cf.z, ci = cf.w;
        bool fwd = (qr <= 0.f);

        float ara, aia, arb, aib, lrS, liS;
        if (fwd) {
            float d0a = (float)l0a, d0b = (float)l0b;
            float ma = expf(qr * d0a), mb = expf(qr * d0b);
            float sa, ca2, sb, cb2;
            sincosf(qi * d0a, &sa, &ca2);
            sincosf(qi * d0b, &sb, &cb2);
            ara = ma * ca2; aia = ma * sa;
            arb = mb * cb2; aib = mb * sb;
            float em = expf(qr);
            float sl, cl2; sincosf(qi, &sl, &cl2);
            lrS = em * cl2; liS = em * sl;
        } else {
            float d0a = (float)(l0a + 31 - (Lq - 1));
            float d0b = (float)(l0b + 31 - (Lq - 1));
            float ma = expf(qr * d0a), mb = expf(qr * d0b);
            float sa, ca2, sb, cb2;
            sincosf(qi * d0a, &sa, &ca2);
            sincosf(qi * d0b, &sb, &cb2);
            ara = ma * ca2; aia = ma * sa;
            arb = mb * cb2; aib = mb * sb;
            float em = expf(-qr);
            float sl, cl2; sincosf(-qi, &sl, &cl2);
            lrS = em * cl2; liS = em * sl;
        }

        ull ar2 = pk2(ara, arb), ai2 = pk2(aia, aib);
        ull lr2 = pk2(lrS, lrS), li2 = pk2(liS, liS);
        ull nli2 = pk2(-liS, -liS);
        ull cr2 = pk2(cr, cr), ci2 = pk2(ci, ci), nci2 = pk2(-ci, -ci);

        {
            ull par = f2fma(cr2, ar2, f2mul(nci2, ai2));
            ull pai = f2fma(cr2, ai2, f2mul(ci2, ar2));
            ar2 = par; ai2 = pai;
        }

        if (fwd) {
#pragma unroll
            for (int j = 0; j < 32; j++) {
                acc[j] = f2add(acc[j], ar2);
                ull t = f2fma(ar2, lr2, f2mul(ai2, nli2));
                ai2 = f2fma(ar2, li2, f2mul(ai2, lr2));
                ar2 = t;
            }
        } else {
#pragma unroll
            for (int j = 31; j >= 0; j--) {
                acc[j] = f2add(acc[j], ar2);
                ull t = f2fma(ar2, lr2, f2mul(ai2, nli2));
                ai2 = f2fma(ar2, li2, f2mul(ai2, lr2));
                ar2 = t;
            }
        }
    }

#pragma unroll
    for (int j = 0; j < 32; j++) {
        float a, b; upk2(acc[j], a, b);
        kbuf[g * 2048 + (cp << 5) + j]        = a;
        kbuf[g * 2048 + 1024 + (cp << 5) + j] = b;
    }
    __syncthreads();
    for (int i = tid; i < 2048; i += 256) {
        float s = 0.f;
#pragma unroll
        for (int gg = 0; gg < 8; gg++) s += kbuf[gg * 2048 + i];
        int l = (i < 1024) ? (half * 1024 + i) : (2048 + half * 1024 + (i - 1024));
        g_K[h * Lq + l] = s;
    }
}

// ---------------- packed FFT stages (X = interleaved {re,im} 16B elements) --------
__device__ __forceinline__ void fft_stage0_regsP(u2* X, int tid, const c2 z[8]) {
    c2 A0[4], A1[4], A2[4], A3[4];
    ALAYER_HALFP(z, A0, A1, A2, A3);
    c2 y[16];
    BLAYER_TWP(A0, A1, A2, A3, y, g_tw[tid << 1]);
    int ob = tid << 4;
#pragma unroll
    for (int m = 0; m < 16; m++) stc(X, PD(ob + m), y[m]);
    __syncthreads();
}

__device__ __forceinline__ void fft_stage1P(u2* X, int tid) {
    int q = tid & 15, pp = tid - q;
    c2 x[16];
#pragma unroll
    for (int r = 0; r < 16; r++) x[r] = ldc(X, PD(tid + (r << 8)));
    __syncthreads();
    c2 A0[4], A1[4], A2[4], A3[4];
    ALAYERP(x, A0, A1, A2, A3);
    c2 y[16];
    BLAYER_TWP(A0, A1, A2, A3, y, g_tw[pp << 1]);
    int ob = (pp << 4) + q;
#pragma unroll
    for (int m = 0; m < 16; m++) stc(X, PD(ob + (m << 4)), y[m]);
    __syncthreads();
}

// forward stage2: keep ALL outputs in regs; store only UPPER half (m>=8) to smem.
__device__ __forceinline__ void fft_stage2_keepP(u2* X, int tid, c2 y[16]) {
    c2 x[16];
#pragma unroll
    for (int r = 0; r < 16; r++) x[r] = ldc(X, PD(tid + (r << 8)));
    c2 A0[4], A1[4], A2[4], A3[4];
    ALAYERP(x, A0, A1, A2, A3);
    BLAYER_UNITP(A0, A1, A2, A3, y);
#pragma unroll
    for (int m = 8; m < 16; m++) stc(X, PD(tid + (m << 8)), y[m]);
    __syncthreads();
}

// inverse stage0: lower 8 inputs from regs (kept S), upper 8 from smem
__device__ __forceinline__ void fft_stage0_mixedP(u2* X, int tid, const c2 S[8]) {
    c2 x[16];
#pragma unroll
    for (int m = 8; m < 16; m++) x[m] = ldc(X, PD(tid + (m << 8)));
#pragma unroll
    for (int m = 0; m < 8; m++) x[m] = S[m];
    __syncthreads();
    c2 A0[4], A1[4], A2[4], A3[4];
    ALAYERP(x, A0, A1, A2, A3);
    c2 y[16];
    BLAYER_TWP(A0, A1, A2, A3, y, g_tw[tid << 1]);
    int ob = tid << 4;
#pragma unroll
    for (int m = 0; m < 16; m++) stc(X, PD(ob + m), y[m]);
    __syncthreads();
}

// ---------------- rfft8192(K) -> G, two h-rows per block ----------------
__global__ __launch_bounds__(256, 2) void fftG_kernel() {
    extern __shared__ u2 smu[];
    u2* X = smu;
    int h0 = blockIdx.x, h1 = h0 + 256;
    int tid = threadIdx.x;
    const float2* kA = (const float2*)(g_K + (size_t)h0 * Lq);
    const float2* kB = (const float2*)(g_K + (size_t)h1 * Lq);
    {
        c2 z[8];
#pragma unroll
        for (int r = 0; r < 8; r++) {
            float2 a = kA[tid + (r << 8)], b = kB[tid + (r << 8)];
            z[r].r = pk2(a.x, b.x);
            z[r].i = pk2(a.y, b.y);
        }
        fft_stage0_regsP(X, tid, z);
    }
    fft_stage1P(X, tid);
    c2 y[16];
    fft_stage2_keepP(X, tid, y);     // lower half kept in y[0..7], upper in smem

    float2* G0 = g_G + (size_t)h0 * GSTRIDE;
    float2* G1 = g_G + (size_t)h1 * GSTRIDE;

    // r = 0 (may hit k==0 special case, only possible here)
    {
        int k = tid;
        if (k == 0) {
            c2 z0 = y[0];
            ull s = f2add(z0.r, z0.i);
            ull d = f2sub(z0.r, z0.i);
            float sa, sb, da, db; upk2(s, sa, sb); upk2(d, da, db);
            G0[0] = make_float2(sa, 0.f);    G1[0] = make_float2(sb, 0.f);
            G0[4096] = make_float2(da, 0.f); G1[4096] = make_float2(db, 0.f);
            c2 z2 = y[8]; z2.i = f2neg(z2.i);
            float ra, rb, ia, ib; upk2(z2.r, ra, rb); upk2(z2.i, ia, ib);
            G0[2048] = make_float2(ra, ia);  G1[2048] = make_float2(rb, ib);
        } else {
            c2 zk = y[0];
            c2 zm = ldc(X, PD(4096 - k));
            ull half = pk2(0.5f, 0.5f), nhalf = pk2(-0.5f, -0.5f);
            c2 xe, xo;
            xe.r = f2mul(f2add(zk.r, zm.r), half);
            xe.i = f2mul(f2sub(zk.i, zm.i), half);
            xo.r = f2mul(f2add(zk.i, zm.i), half);
            xo.i = f2mul(f2sub(zk.r, zm.r), nhalf);
            float2 w = g_tw[k];
            c2 wxo = c2mulw(xo, w);
            c2 gf, gb;
            gf.r = f2add(xe.r, wxo.r); gf.i = f2add(xe.i, wxo.i);
            gb.r = f2sub(xe.r, wxo.r); gb.i = f2neg(f2sub(xe.i, wxo.i));
            float ra, rb, ia, ib;
            upk2(gf.r, ra, rb); upk2(gf.i, ia, ib);
            G0[k] = make_float2(ra, ia); G1[k] = make_float2(rb, ib);
            upk2(gb.r, ra, rb); upk2(gb.i, ia, ib);
            G0[4096 - k] = make_float2(ra, ia); G1[4096 - k] = make_float2(rb, ib);
        }
    }
    // r = 1..7 branch-free
#pragma unroll
    for (int r = 1; r < 8; r++) {
        int k = tid + (r << 8);
        c2 zk = y[r];
        c2 zm = ldc(X, PD(4096 - k));
        ull half = pk2(0.5f, 0.5f), nhalf = pk2(-0.5f, -0.5f);
        c2 xe, xo;
        xe.r = f2mul(f2add(zk.r, zm.r), half);
        xe.i = f2mul(f2sub(zk.i, zm.i), half);
        xo.r = f2mul(f2add(zk.i, zm.i), half);
        xo.i = f2mul(f2sub(zk.r, zm.r), nhalf);
        float2 w = g_tw[k];
        c2 wxo = c2mulw(xo, w);
        c2 gf, gb;
        gf.r = f2add(xe.r, wxo.r); gf.i = f2add(xe.i, wxo.i);
        gb.r = f2sub(xe.r, wxo.r); gb.i = f2neg(f2sub(xe.i, wxo.i));
        float ra, rb, ia, ib;
        upk2(gf.r, ra, rb); upk2(gf.i, ia, ib);
        G0[k] = make_float2(ra, ia); G1[k] = make_float2(rb, ib);
        upk2(gb.r, ra, rb); upk2(gb.i, ia, ib);
        G0[4096 - k] = make_float2(ra, ia); G1[4096 - k] = make_float2(rb, ib);
    }
}

// ---------------- conv: two (b,h) rows per block, fully f32x2 packed --------------
__global__ __launch_bounds__(256, 2) void conv_kernel(const float* __restrict__ u,
                                                      const float* __restrict__ D,
                                                      float* __restrict__ out) {
    extern __shared__ u2 smu[];
    u2* X = smu;
    int blk = blockIdx.x;                 // 0..2047
    int h   = blk & (Hh - 1);
    int bp  = blk >> 9;                   // 0..3
    size_t rowA = (size_t)(2 * bp) * Hh + h;
    size_t rowB = rowA + Hh;
    int tid = threadIdx.x;
    const float2* uA = (const float2*)(u + rowA * Lq);
    const float2* uB = (const float2*)(u + rowB * Lq);

    // forward FFT (packed real input, upper half zero); u NOT cached in regs
    {
        c2 z[8];
#pragma unroll
        for (int r = 0; r < 8; r++) {
            float2 a = uA[tid + (r << 8)], b = uB[tid + (r << 8)];
            z[r].r = pk2(a.x, b.x);
            z[r].i = pk2(a.y, b.y);
        }
        fft_stage0_regsP(X, tid, z);
    }
    fft_stage1P(X, tid);
    c2 y[16];
    fft_stage2_keepP(X, tid, y);     // lower kept in y[0..7], upper in smem (+regs)

    // middle: prefetch G (L2), read upper partners from smem, sync, compute.
    const float2* G = g_G + (size_t)h * GSTRIDE;
    float2 gk[8], gm[8];
#pragma unroll
    for (int r = 0; r < 8; r++) {
        int k = tid + (r << 8);
        if (k == 0) { gk[0] = G[0]; gm[0] = G[4096]; }
        else        { gk[r] = G[k]; gm[r] = G[4096 - k]; }
    }
    float2 g2048; if (tid == 0) g2048 = G[2048];

    c2 sb[8];
#pragma unroll
    for (int r = 0; r < 8; r++) {
        int k = tid + (r << 8);
        if (k == 0) { sb[r].r = 0ULL; sb[r].i = 0ULL; }
        else        { sb[r] = ldc(X, PD(4096 - k)); }
    }
    __syncthreads();

    c2 S[8];                          // kept lower outputs (conj-stored ifft inputs)
    // r = 0 (k==0 only possible here)
    {
        int k = tid;
        ull half = pk2(0.5f, 0.5f), nhalf = pk2(-0.5f, -0.5f);
        if (k == 0) {
            c2 z0 = y[0];
            ull x0 = f2add(z0.r, z0.i);
            ull xM = f2sub(z0.r, z0.i);
            ull y0 = f2mul(x0, pk2(gk[0].x, gk[0].x));
            ull yM = f2mul(xM, pk2(gm[0].x, gm[0].x));
            S[0].r = f2mul(f2add(y0, yM), half);
            S[0].i = f2mul(f2sub(y0, yM), nhalf);
            c2 t; t.r = y[8].r; t.i = f2neg(y[8].i);     // Z[2048] = own y[8]
            stc(X, PD(2048), c2mulw(t, g2048));
        } else {
            c2 zk = y[0], zm = sb[0];
            c2 xe, xo;
            xe.r = f2mul(f2add(zk.r, zm.r), half);
            xe.i = f2mul(f2sub(zk.i, zm.i), half);
            xo.r = f2mul(f2add(zk.i, zm.i), half);
            xo.i = f2mul(f2sub(zk.r, zm.r), nhalf);
            float2 w = g_tw[k];
            c2 wxo = c2mulw(xo, w);
            c2 xf, xb;
            xf.r = f2add(xe.r, wxo.r); xf.i = f2add(xe.i, wxo.i);
            xb.r = f2sub(xe.r, wxo.r); xb.i = f2neg(f2sub(xe.i, wxo.i));
            c2 ya = c2mulw(xf, gk[0]);
            c2 yb = c2mulw(xb, gm[0]);
            c2 ye, dd;
            ye.r = f2mul(f2add(ya.r, yb.r), half);
            ye.i = f2mul(f2sub(ya.i, yb.i), half);
            dd.r = f2sub(ya.r, yb.r);
            dd.i = f2add(ya.i, yb.i);
            c2 yo = c2mulw(dd, make_float2(w.x, -w.y));
            yo.r = f2mul(yo.r, half); yo.i = f2mul(yo.i, half);
            S[0].r = f2sub(ye.r, yo.i);
            S[0].i = f2neg(f2add(ye.i, yo.r));
            c2 ob2;
            ob2.r = f2add(ye.r, yo.i);
            ob2.i = f2sub(ye.i, yo.r);
            stc(X, PD(4096 - k), ob2);
        }
    }
    // r = 1..7 branch-free (k = tid + 256r != 0 always)
#pragma unroll
    for (int r = 1; r < 8; r++) {
        int k = tid + (r << 8);
        ull half = pk2(0.5f, 0.5f), nhalf = pk2(-0.5f, -0.5f);
        c2 zk = y[r], zm = sb[r];
        c2 xe, xo;
        xe.r = f2mul(f2add(zk.r, zm.r), half);
        xe.i = f2mul(f2sub(zk.i, zm.i), half);
        xo.r = f2mul(f2add(zk.i, zm.i), half);
        xo.i = f2mul(f2sub(zk.r, zm.r), nhalf);
        float2 w = g_tw[k];
        c2 wxo = c2mulw(xo, w);
        c2 xf, xb;
        xf.r = f2add(xe.r, wxo.r); xf.i = f2add(xe.i, wxo.i);
        xb.r = f2sub(xe.r, wxo.r); xb.i = f2neg(f2sub(xe.i, wxo.i));
        c2 ya = c2mulw(xf, gk[r]);
        c2 yb = c2mulw(xb, gm[r]);
        c2 ye, dd;
        ye.r = f2mul(f2add(ya.r, yb.r), half);
        ye.i = f2mul(f2sub(ya.i, yb.i), half);
        dd.r = f2sub(ya.r, yb.r);
        dd.i = f2add(ya.i, yb.i);
        c2 yo = c2mulw(dd, make_float2(w.x, -w.y));
        yo.r = f2mul(yo.r, half); yo.i = f2mul(yo.i, half);
        S[r].r = f2sub(ye.r, yo.i);
        S[r].i = f2neg(f2add(ye.i, yo.r));
        c2 ob2;
        ob2.r = f2add(ye.r, yo.i);
        ob2.i = f2sub(ye.i, yo.r);
        stc(X, PD(4096 - k), ob2);
    }
    __syncthreads();

    // inverse FFT: stage0 mixed (lower from regs, upper from smem)
    fft_stage0_mixedP(X, tid, S);
    fft_stage1P(X, tid);
    {
        c2 x[16];
#pragma unroll
        for (int r = 0; r < 16; r++) x[r] = ldc(X, PD(tid + (r << 8)));
        c2 A0[4], A1[4], A2[4], A3[4];
        ALAYERP(x, A0, A1, A2, A3);
        c2 yf[8];
        BLAYER_UNIT_HALFP(A0, A1, A2, A3, yf);

        float dh = D[h];
        ull dh2 = pk2(dh, dh);
        ull inv2 = pk2(1.0f / Mh, 1.0f / Mh);
        ull ninv2 = pk2(-1.0f / Mh, -1.0f / Mh);
        float2* oA = (float2*)(out + rowA * Lq);
        float2* oB = (float2*)(out + rowB * Lq);
#pragma unroll
        for (int m = 0; m < 8; m++) {
            float2 a = uA[tid + (m << 8)], b = uB[tid + (m << 8)];   // L2 reload
            ull urr = pk2(a.x, b.x), uri = pk2(a.y, b.y);
            ull resr = f2fma(urr, dh2, f2mul(yf[m].r, inv2));
            ull resi = f2fma(uri, dh2, f2mul(yf[m].i, ninv2));
            float ra, rb, ia, ib;
            upk2(resr, ra, rb); upk2(resi, ia, ib);
            oA[tid + (m << 8)] = make_float2(ra, ia);
            oB[tid + (m << 8)] = make_float2(rb, ib);
        }
    }
}

// ---------------- launcher ----------------
extern "C" void kernel_launch(void* const* d_in, const int* in_sizes, int n_in,
                              void* d_out, int out_size) {
    const float* u  = (const float*)d_in[0];
    const float* W  = (const float*)d_in[1];
    const float* D  = (const float*)d_in[2];
    const float* ls = (const float*)d_in[3];
    const float* Lr = (const float*)d_in[4];
    const float* Li = (const float*)d_in[5];
    float* out = (float*)d_out;

    int fft_smem = PDN * (int)sizeof(u2);             // 69632 B
    int k_smem   = 8 * 2048 * (int)sizeof(float);     // 65536 B

    cudaFuncSetAttribute(k_kernel,    cudaFuncAttributeMaxDynamicSharedMemorySize, k_smem);
    cudaFuncSetAttribute(fftG_kernel, cudaFuncAttributeMaxDynamicSharedMemorySize, fft_smem);
    cudaFuncSetAttribute(conv_kernel, cudaFuncAttributeMaxDynamicSharedMemorySize, fft_smem);

    setup_kernel<<<16 + Hh, 256>>>(W, ls, Lr, Li);
    k_kernel<<<2 * Hh, 256, k_smem>>>();
    fftG_kernel<<<Hh / 2, 256, fft_smem>>>();
    conv_kernel<<<Bb * Hh / 2, 256, fft_smem>>>(u, D, out);
}

// round 17
// speedup vs baseline: 1.0571x; 1.0371x over previous
#include <cuda_runtime.h>
#include <math.h>

#define Lq   4096
#define NFFT 8192
#define Mh   4096
#define Hh   512
#define Bb   8
#define Nn   64
#define GSTRIDE 4104

typedef unsigned long long ull;
typedef ulonglong2 u2;

__device__ float  g_K[Hh * Lq];
__device__ float2 g_G[Hh * GSTRIDE];
__device__ float2 g_tw[NFFT / 2];        // W_8192^j, j<4096
__device__ float4 g_coef[Hh * Nn];

#define PD(i) ((i) + ((i) >> 4))
#define PDN 4352

// ---------------- scalar complex helpers (twiddle chains only) ----------------
__device__ __forceinline__ float2 cmulf(float2 a, float2 b) {
    return make_float2(fmaf(a.x, b.x, -a.y * b.y), fmaf(a.x, b.y, a.y * b.x));
}

// ---------------- f32x2 packed primitives ----------------
__device__ __forceinline__ ull pk2(float lo, float hi){
    ull r; asm("mov.b64 %0,{%1,%2};":"=l"(r):"f"(lo),"f"(hi)); return r;
}
__device__ __forceinline__ void upk2(ull v, float& lo, float& hi){
    asm("mov.b64 {%0,%1},%2;":"=f"(lo),"=f"(hi):"l"(v));
}
__device__ __forceinline__ ull f2add(ull a, ull b){
    ull r; asm("add.rn.f32x2 %0,%1,%2;":"=l"(r):"l"(a),"l"(b)); return r;
}
__device__ __forceinline__ ull f2mul(ull a, ull b){
    ull r; asm("mul.rn.f32x2 %0,%1,%2;":"=l"(r):"l"(a),"l"(b)); return r;
}
__device__ __forceinline__ ull f2fma(ull a, ull b, ull c){
    ull r; asm("fma.rn.f32x2 %0,%1,%2,%3;":"=l"(r):"l"(a),"l"(b),"l"(c)); return r;
}
__device__ __forceinline__ ull f2sub(ull a, ull b){ return f2fma(b, pk2(-1.f,-1.f), a); }
__device__ __forceinline__ ull f2neg(ull a){ return f2mul(a, pk2(-1.f,-1.f)); }

// two-row packed complex: r = (reA, reB), i = (imA, imB)
struct c2 { ull r, i; };

__device__ __forceinline__ c2 ldc(const u2* X, int idx){ u2 v = X[idx]; c2 o; o.r = v.x; o.i = v.y; return o; }
__device__ __forceinline__ void stc(u2* X, int idx, c2 v){ X[idx] = make_ulonglong2(v.r, v.i); }

__device__ __forceinline__ c2 c2add(c2 a, c2 b){ c2 o; o.r=f2add(a.r,b.r); o.i=f2add(a.i,b.i); return o; }
__device__ __forceinline__ c2 c2sub(c2 a, c2 b){ c2 o; o.r=f2sub(a.r,b.r); o.i=f2sub(a.i,b.i); return o; }
__device__ __forceinline__ c2 c2mulw(c2 a, float2 w){
    ull wr = pk2(w.x, w.x), wi = pk2(w.y, w.y), nwi = pk2(-w.y, -w.y);
    c2 o;
    o.r = f2fma(a.r, wr, f2mul(a.i, nwi));
    o.i = f2fma(a.r, wi, f2mul(a.i, wr));
    return o;
}
__device__ __forceinline__ c2 c2mulni(c2 a){ c2 o; o.r = a.i; o.i = f2neg(a.r); return o; }

// ---------------- packed DFT4s ----------------
#define DFT4P(p0,p1,p2,p3,q0,q1,q2,q3) { \
    c2 t0=c2add(p0,p2), t1=c2sub(p0,p2), t2=c2add(p1,p3), t3=c2sub(p1,p3); \
    q0=c2add(t0,t2); q2=c2sub(t0,t2); \
    q1.r=f2add(t1.r,t3.i); q1.i=f2sub(t1.i,t3.r); \
    q3.r=f2sub(t1.r,t3.i); q3.i=f2add(t1.i,t3.r); }

#define DFT4HP(p0,p1,q0,q1,q2,q3) { \
    q0=c2add(p0,p1); q2=c2sub(p0,p1); \
    q1.r=f2add(p0.r,p1.i); q1.i=f2sub(p0.i,p1.r); \
    q3.r=f2sub(p0.r,p1.i); q3.i=f2add(p0.i,p1.r); }

#define DFT4_01P(p0,p1,p2,p3,q0,q1) { \
    c2 t0=c2add(p0,p2), t1=c2sub(p0,p2), t2=c2add(p1,p3), t3=c2sub(p1,p3); \
    q0=c2add(t0,t2); \
    q1.r=f2add(t1.r,t3.i); q1.i=f2sub(t1.i,t3.r); }

#define W16_1 make_float2( 0.9238795325112867f, -0.3826834323650898f)
#define W16_2 make_float2( 0.7071067811865476f, -0.7071067811865476f)
#define W16_3 make_float2( 0.3826834323650898f, -0.9238795325112867f)
#define W16_6 make_float2(-0.7071067811865476f, -0.7071067811865476f)
#define W16_9 make_float2(-0.9238795325112867f,  0.3826834323650898f)

#define ALAYERP(x,A0,A1,A2,A3) { \
    DFT4P(x[0],x[4],x[8],x[12], A0[0],A0[1],A0[2],A0[3]); \
    DFT4P(x[1],x[5],x[9],x[13], A1[0],A1[1],A1[2],A1[3]); \
    DFT4P(x[2],x[6],x[10],x[14],A2[0],A2[1],A2[2],A2[3]); \
    DFT4P(x[3],x[7],x[11],x[15],A3[0],A3[1],A3[2],A3[3]); }

#define ALAYER_HALFP(z,A0,A1,A2,A3) { \
    DFT4HP(z[0],z[4],A0[0],A0[1],A0[2],A0[3]); \
    DFT4HP(z[1],z[5],A1[0],A1[1],A1[2],A1[3]); \
    DFT4HP(z[2],z[6],A2[0],A2[1],A2[2],A2[3]); \
    DFT4HP(z[3],z[7],A3[0],A3[1],A3[2],A3[3]); }

#define BLAYER_TWP(A0,A1,A2,A3,y,W1IN) { \
    float2 w1=(W1IN); \
    float2 w2=cmulf(w1,w1), w3=cmulf(w2,w1), w4=cmulf(w2,w2); \
    float2 w8=cmulf(w4,w4), w12=cmulf(w8,w4); \
    DFT4P(A0[0],A1[0],A2[0],A3[0], y[0],y[4],y[8],y[12]); \
    { c2 v0=c2mulw(A0[1],w1); \
      c2 v1=c2mulw(A1[1],cmulf(W16_1,w1)); \
      c2 v2=c2mulw(A2[1],cmulf(W16_2,w1)); \
      c2 v3=c2mulw(A3[1],cmulf(W16_3,w1)); \
      DFT4P(v0,v1,v2,v3, y[1],y[5],y[9],y[13]); } \
    { c2 v0=c2mulw(A0[2],w2); \
      c2 v1=c2mulw(A1[2],cmulf(W16_2,w2)); \
      c2 v2=c2mulw(A2[2],make_float2(w2.y,-w2.x)); \
      c2 v3=c2mulw(A3[2],cmulf(W16_6,w2)); \
      DFT4P(v0,v1,v2,v3, y[2],y[6],y[10],y[14]); } \
    { c2 v0=c2mulw(A0[3],w3); \
      c2 v1=c2mulw(A1[3],cmulf(W16_3,w3)); \
      c2 v2=c2mulw(A2[3],cmulf(W16_6,w3)); \
      c2 v3=c2mulw(A3[3],cmulf(W16_9,w3)); \
      DFT4P(v0,v1,v2,v3, y[3],y[7],y[11],y[15]); } \
    _Pragma("unroll") \
    for (int m1=0;m1<4;m1++){ \
        y[m1+4]=c2mulw(y[m1+4],w4); y[m1+8]=c2mulw(y[m1+8],w8); y[m1+12]=c2mulw(y[m1+12],w12); } }

#define BLAYER_UNITP(A0,A1,A2,A3,y) { \
    DFT4P(A0[0],A1[0],A2[0],A3[0], y[0],y[4],y[8],y[12]); \
    { c2 v1=c2mulw(A1[1],W16_1), v2=c2mulw(A2[1],W16_2), v3=c2mulw(A3[1],W16_3); \
      DFT4P(A0[1],v1,v2,v3, y[1],y[5],y[9],y[13]); } \
    { c2 v1=c2mulw(A1[2],W16_2); \
      c2 v2=c2mulni(A2[2]); \
      c2 v3=c2mulw(A3[2],W16_6); \
      DFT4P(A0[2],v1,v2,v3, y[2],y[6],y[10],y[14]); } \
    { c2 v1=c2mulw(A1[3],W16_3), v2=c2mulw(A2[3],W16_6), v3=c2mulw(A3[3],W16_9); \
      DFT4P(A0[3],v1,v2,v3, y[3],y[7],y[11],y[15]); } }

#define BLAYER_UNIT_HALFP(A0,A1,A2,A3,y) { \
    DFT4_01P(A0[0],A1[0],A2[0],A3[0], y[0],y[4]); \
    { c2 v1=c2mulw(A1[1],W16_1), v2=c2mulw(A2[1],W16_2), v3=c2mulw(A3[1],W16_3); \
      DFT4_01P(A0[1],v1,v2,v3, y[1],y[5]); } \
    { c2 v1=c2mulw(A1[2],W16_2); \
      c2 v2=c2mulni(A2[2]); \
      c2 v3=c2mulw(A3[2],W16_6); \
      DFT4_01P(A0[2],v1,v2,v3, y[2],y[6]); } \
    { c2 v1=c2mulw(A1[3],W16_3), v2=c2mulw(A2[3],W16_6), v3=c2mulw(A3[3],W16_9); \
      DFT4_01P(A0[3],v1,v2,v3, y[3],y[7]); } }

// ---------------- setup: twiddles (blocks 0..15) + coeffs (blocks 16..527) --------
__global__ void setup_kernel(const float* __restrict__ W,
                             const float* __restrict__ log_step,
                             const float* __restrict__ Lre,
                             const float* __restrict__ Lim) {
    if (blockIdx.x < 16) {
        int j = blockIdx.x * 256 + threadIdx.x;
        if (j < NFFT / 2) {
            float s, c;
            sincospif(-(float)j * (1.0f / 4096.0f), &s, &c);
            g_tw[j] = make_float2(c, s);
        }
        return;
    }
    int h = blockIdx.x - 16;
    int n = threadIdx.x;
    if (n >= Nn) return;
    float step = expf(log_step[h]);
    float Lr = Lre[n], Li = Lim[n];
    float qr = step * Lr, qi = step * Li;

    double sgn = (qr > 0.f) ? -1.0 : 1.0;
    double pr = sgn * (double)qr, pi = sgn * (double)qi;

    double eL = exp(pr * (double)Lq);
    double sL, cL;
    sincos(pi * (double)Lq, &sL, &cL);
    double num_re = eL * cL - 1.0;
    double num_im = eL * sL;

    double sp, cp;
    sincos(pi, &sp, &cp);
    double em1 = expm1(pr);
    double hs  = sin(0.5 * pi);
    double den_re = em1 * cp - 2.0 * hs * hs;
    double den_im = (em1 + 1.0) * sp;
    double dmag = den_re * den_re + den_im * den_im;

    double s_re, s_im;
    if (dmag > 0.0) {
        s_re = (num_re * den_re + num_im * den_im) / dmag;
        s_im = (num_im * den_re - num_re * den_im) / dmag;
    } else {
        s_re = (double)Lq;
        s_im = 0.0;
    }

    double w0 = W[(h * Nn + n) * 2 + 0];
    double w1 = W[(h * Nn + n) * 2 + 1];
    double lmag = (double)Lr * Lr + (double)Li * Li;
    double a_re = (w0 * Lr + w1 * Li) / lmag;
    double a_im = (w1 * Lr - w0 * Li) / lmag;
    double smag = s_re * s_re + s_im * s_im + 1e-7;
    double b_re =  s_re / smag;
    double b_im = -s_im / smag;
    float cr = (float)(a_re * b_re - a_im * b_im);
    float ci = (float)(a_re * b_im + a_im * b_re);
    g_coef[h * Nn + n] = make_float4(qr, qi, cr, ci);
}

// ---------------- K: real Chebyshev recurrence x_{l+1}=2Re(lam)x_l - |lam|^2 x_{l-1}
// 3 packed ops per j (was 5). Seeds from the complex folded anchor; decaying
// direction in both branches (spectral radius <= 1 -> stable).
__global__ __launch_bounds__(256) void k_kernel() {
    extern __shared__ float kbuf[];     // 8 * 2048 floats = 64KB
    int blk  = blockIdx.x;
    int h    = blk >> 1;
    int half = blk & 1;
    int tid  = threadIdx.x;
    int cp   = tid & 31;
    int g    = tid >> 5;
    int l0a  = (half * 32 + cp) * 32;
    int l0b  = l0a + 2048;

    ull acc[32];
#pragma unroll
    for (int j = 0; j < 32; j++) acc[j] = 0ULL;

    for (int nn = 0; nn < 8; nn++) {
        int n = (g << 3) + nn;
        float4 cf = g_coef[h * Nn + n];
        float qr = cf.x, qi = cf.y, cr = cf.z, ci = cf.w;
        bool fwd = (qr <= 0.f);

        float ara, aia, arb, aib, lrS, liS;
        if (fwd) {
            float d0a = (float)l0a, d0b = (float)l0b;
            float ma = expf(qr * d0a), mb = expf(qr * d0b);
            float sa, ca2, sb, cb2;
            sincosf(qi * d0a, &sa, &ca2);
            sincosf(qi * d0b, &sb, &cb2);
            ara = ma * ca2; aia = ma * sa;
            arb = mb * cb2; aib = mb * sb;
            float em = expf(qr);
            float sl, cl2; sincosf(qi, &sl, &cl2);
            lrS = em * cl2; liS = em * sl;
        } else {
            float d0a = (float)(l0a + 31 - (Lq - 1));
            float d0b = (float)(l0b + 31 - (Lq - 1));
            float ma = expf(qr * d0a), mb = expf(qr * d0b);
            float sa, ca2, sb, cb2;
            sincosf(qi * d0a, &sa, &ca2);
            sincosf(qi * d0b, &sb, &cb2);
            ara = ma * ca2; aia = ma * sa;
            arb = mb * cb2; aib = mb * sb;
            float em = expf(-qr);
            float sl, cl2; sincosf(-qi, &sl, &cl2);
            lrS = em * cl2; liS = em * sl;
        }

        ull ar2 = pk2(ara, arb), ai2 = pk2(aia, aib);
        ull lr2 = pk2(lrS, lrS);
        ull nli2 = pk2(-liS, -liS);
        ull cr2 = pk2(cr, cr), ci2 = pk2(ci, ci), nci2 = pk2(-ci, -ci);

        // fold coefficient into anchor: a' = c * a
        {
            ull par = f2fma(cr2, ar2, f2mul(nci2, ai2));
            ull pai = f2fma(cr2, ai2, f2mul(ci2, ar2));
            ar2 = par; ai2 = pai;
        }

        // Chebyshev constants: c1 = 2*Re(lam_step), nrho2 = -|lam_step|^2
        ull li2 = pk2(liS, liS);
        ull c1    = f2add(lr2, lr2);
        ull nrho2 = f2neg(f2fma(lr2, lr2, f2mul(li2, li2)));

        // seeds: x0 = Re(a'), x1 = Re(a' * lam_step)
        ull x0 = ar2;
        ull x1 = f2fma(ar2, lr2, f2mul(ai2, nli2));

        if (fwd) {
            acc[0] = f2add(acc[0], x0);
            acc[1] = f2add(acc[1], x1);
#pragma unroll
            for (int j = 2; j < 32; j++) {
                ull xn = f2fma(c1, x1, f2mul(x0, nrho2));
                acc[j] = f2add(acc[j], xn);
                x0 = x1; x1 = xn;
            }
        } else {
            // anchor at j=31; step is lam^{-1} (decaying since qr>0)
            acc[31] = f2add(acc[31], x0);
            acc[30] = f2add(acc[30], x1);
#pragma unroll
            for (int j = 29; j >= 0; j--) {
                ull xn = f2fma(c1, x1, f2mul(x0, nrho2));
                acc[j] = f2add(acc[j], xn);
                x0 = x1; x1 = xn;
            }
        }
    }

#pragma unroll
    for (int j = 0; j < 32; j++) {
        float a, b; upk2(acc[j], a, b);
        kbuf[g * 2048 + (cp << 5) + j]        = a;
        kbuf[g * 2048 + 1024 + (cp << 5) + j] = b;
    }
    __syncthreads();
    for (int i = tid; i < 2048; i += 256) {
        float s = 0.f;
#pragma unroll
        for (int gg = 0; gg < 8; gg++) s += kbuf[gg * 2048 + i];
        int l = (i < 1024) ? (half * 1024 + i) : (2048 + half * 1024 + (i - 1024));
        g_K[h * Lq + l] = s;
    }
}

// ---------------- packed FFT stages (X = interleaved {re,im} 16B elements) --------
__device__ __forceinline__ void fft_stage0_regsP(u2* X, int tid, const c2 z[8]) {
    c2 A0[4], A1[4], A2[4], A3[4];
    ALAYER_HALFP(z, A0, A1, A2, A3);
    c2 y[16];
    BLAYER_TWP(A0, A1, A2, A3, y, g_tw[tid << 1]);
    int ob = tid << 4;
#pragma unroll
    for (int m = 0; m < 16; m++) stc(X, PD(ob + m), y[m]);
    __syncthreads();
}

__device__ __forceinline__ void fft_stage1P(u2* X, int tid) {
    int q = tid & 15, pp = tid - q;
    c2 x[16];
#pragma unroll
    for (int r = 0; r < 16; r++) x[r] = ldc(X, PD(tid + (r << 8)));
    __syncthreads();
    c2 A0[4], A1[4], A2[4], A3[4];
    ALAYERP(x, A0, A1, A2, A3);
    c2 y[16];
    BLAYER_TWP(A0, A1, A2, A3, y, g_tw[pp << 1]);
    int ob = (pp << 4) + q;
#pragma unroll
    for (int m = 0; m < 16; m++) stc(X, PD(ob + (m << 4)), y[m]);
    __syncthreads();
}

// forward stage2: keep ALL outputs in regs; store only UPPER half (m>=8) to smem.
__device__ __forceinline__ void fft_stage2_keepP(u2* X, int tid, c2 y[16]) {
    c2 x[16];
#pragma unroll
    for (int r = 0; r < 16; r++) x[r] = ldc(X, PD(tid + (r << 8)));
    c2 A0[4], A1[4], A2[4], A3[4];
    ALAYERP(x, A0, A1, A2, A3);
    BLAYER_UNITP(A0, A1, A2, A3, y);
#pragma unroll
    for (int m = 8; m < 16; m++) stc(X, PD(tid + (m << 8)), y[m]);
    __syncthreads();
}

// inverse stage0: lower 8 inputs from regs (kept S), upper 8 from smem
__device__ __forceinline__ void fft_stage0_mixedP(u2* X, int tid, const c2 S[8]) {
    c2 x[16];
#pragma unroll
    for (int m = 8; m < 16; m++) x[m] = ldc(X, PD(tid + (m << 8)));
#pragma unroll
    for (int m = 0; m < 8; m++) x[m] = S[m];
    __syncthreads();
    c2 A0[4], A1[4], A2[4], A3[4];
    ALAYERP(x, A0, A1, A2, A3);
    c2 y[16];
    BLAYER_TWP(A0, A1, A2, A3, y, g_tw[tid << 1]);
    int ob = tid << 4;
#pragma unroll
    for (int m = 0; m < 16; m++) stc(X, PD(ob + m), y[m]);
    __syncthreads();
}

// ---------------- rfft8192(K) -> G, two h-rows per block ----------------
__global__ __launch_bounds__(256, 2) void fftG_kernel() {
    extern __shared__ u2 smu[];
    u2* X = smu;
    int h0 = blockIdx.x, h1 = h0 + 256;
    int tid = threadIdx.x;
    const float2* kA = (const float2*)(g_K + (size_t)h0 * Lq);
    const float2* kB = (const float2*)(g_K + (size_t)h1 * Lq);
    {
        c2 z[8];
#pragma unroll
        for (int r = 0; r < 8; r++) {
            float2 a = kA[tid + (r << 8)], b = kB[tid + (r << 8)];
            z[r].r = pk2(a.x, b.x);
            z[r].i = pk2(a.y, b.y);
        }
        fft_stage0_regsP(X, tid, z);
    }
    fft_stage1P(X, tid);
    c2 y[16];
    fft_stage2_keepP(X, tid, y);     // lower half kept in y[0..7], upper in smem

    float2* G0 = g_G + (size_t)h0 * GSTRIDE;
    float2* G1 = g_G + (size_t)h1 * GSTRIDE;

    // r = 0 (may hit k==0 special case, only possible here)
    {
        int k = tid;
        if (k == 0) {
            c2 z0 = y[0];
            ull s = f2add(z0.r, z0.i);
            ull d = f2sub(z0.r, z0.i);
            float sa, sb, da, db; upk2(s, sa, sb); upk2(d, da, db);
            G0[0] = make_float2(sa, 0.f);    G1[0] = make_float2(sb, 0.f);
            G0[4096] = make_float2(da, 0.f); G1[4096] = make_float2(db, 0.f);
            c2 z2 = y[8]; z2.i = f2neg(z2.i);
            float ra, rb, ia, ib; upk2(z2.r, ra, rb); upk2(z2.i, ia, ib);
            G0[2048] = make_float2(ra, ia);  G1[2048] = make_float2(rb, ib);
        } else {
            c2 zk = y[0];
            c2 zm = ldc(X, PD(4096 - k));
            ull half = pk2(0.5f, 0.5f), nhalf = pk2(-0.5f, -0.5f);
            c2 xe, xo;
            xe.r = f2mul(f2add(zk.r, zm.r), half);
            xe.i = f2mul(f2sub(zk.i, zm.i), half);
            xo.r = f2mul(f2add(zk.i, zm.i), half);
            xo.i = f2mul(f2sub(zk.r, zm.r), nhalf);
            float2 w = g_tw[k];
            c2 wxo = c2mulw(xo, w);
            c2 gf, gb;
            gf.r = f2add(xe.r, wxo.r); gf.i = f2add(xe.i, wxo.i);
            gb.r = f2sub(xe.r, wxo.r); gb.i = f2neg(f2sub(xe.i, wxo.i));
            float ra, rb, ia, ib;
            upk2(gf.r, ra, rb); upk2(gf.i, ia, ib);
            G0[k] = make_float2(ra, ia); G1[k] = make_float2(rb, ib);
            upk2(gb.r, ra, rb); upk2(gb.i, ia, ib);
            G0[4096 - k] = make_float2(ra, ia); G1[4096 - k] = make_float2(rb, ib);
        }
    }
    // r = 1..7 branch-free
#pragma unroll
    for (int r = 1; r < 8; r++) {
        int k = tid + (r << 8);
        c2 zk = y[r];
        c2 zm = ldc(X, PD(4096 - k));
        ull half = pk2(0.5f, 0.5f), nhalf = pk2(-0.5f, -0.5f);
        c2 xe, xo;
        xe.r = f2mul(f2add(zk.r, zm.r), half);
        xe.i = f2mul(f2sub(zk.i, zm.i), half);
        xo.r = f2mul(f2add(zk.i, zm.i), half);
        xo.i = f2mul(f2sub(zk.r, zm.r), nhalf);
        float2 w = g_tw[k];
        c2 wxo = c2mulw(xo, w);
        c2 gf, gb;
        gf.r = f2add(xe.r, wxo.r); gf.i = f2add(xe.i, wxo.i);
        gb.r = f2sub(xe.r, wxo.r); gb.i = f2neg(f2sub(xe.i, wxo.i));
        float ra, rb, ia, ib;
        upk2(gf.r, ra, rb); upk2(gf.i, ia, ib);
        G0[k] = make_float2(ra, ia); G1[k] = make_float2(rb, ib);
        upk2(gb.r, ra, rb); upk2(gb.i, ia, ib);
        G0[4096 - k] = make_float2(ra, ia); G1[4096 - k] = make_float2(rb, ib);
    }
}

// ---------------- conv: two (b,h) rows per block, fully f32x2 packed --------------
__global__ __launch_bounds__(256, 2) void conv_kernel(const float* __restrict__ u,
                                                      const float* __restrict__ D,
                                                      float* __restrict__ out) {
    extern __shared__ u2 smu[];
    u2* X = smu;
    int blk = blockIdx.x;                 // 0..2047
    int h   = blk & (Hh - 1);
    int bp  = blk >> 9;                   // 0..3
    size_t rowA = (size_t)(2 * bp) * Hh + h;
    size_t rowB = rowA + Hh;
    int tid = threadIdx.x;
    const float2* uA = (const float2*)(u + rowA * Lq);
    const float2* uB = (const float2*)(u + rowB * Lq);

    // forward FFT (packed real input, upper half zero); u NOT cached in regs
    {
        c2 z[8];
#pragma unroll
        for (int r = 0; r < 8; r++) {
            float2 a = uA[tid + (r << 8)], b = uB[tid + (r << 8)];
            z[r].r = pk2(a.x, b.x);
            z[r].i = pk2(a.y, b.y);
        }
        fft_stage0_regsP(X, tid, z);
    }
    fft_stage1P(X, tid);
    c2 y[16];
    fft_stage2_keepP(X, tid, y);     // lower kept in y[0..7], upper in smem (+regs)

    // middle: prefetch G (L2), read upper partners from smem, sync, compute.
    const float2* G = g_G + (size_t)h * GSTRIDE;
    float2 gk[8], gm[8];
#pragma unroll
    for (int r = 0; r < 8; r++) {
        int k = tid + (r << 8);
        if (k == 0) { gk[0] = G[0]; gm[0] = G[4096]; }
        else        { gk[r] = G[k]; gm[r] = G[4096 - k]; }
    }
    float2 g2048; if (tid == 0) g2048 = G[2048];

    c2 sb[8];
#pragma unroll
    for (int r = 0; r < 8; r++) {
        int k = tid + (r << 8);
        if (k == 0) { sb[r].r = 0ULL; sb[r].i = 0ULL; }
        else        { sb[r] = ldc(X, PD(4096 - k)); }
    }
    __syncthreads();

    c2 S[8];                          // kept lower outputs (conj-stored ifft inputs)
    // r = 0 (k==0 only possible here)
    {
        int k = tid;
        ull half = pk2(0.5f, 0.5f), nhalf = pk2(-0.5f, -0.5f);
        if (k == 0) {
            c2 z0 = y[0];
            ull x0 = f2add(z0.r, z0.i);
            ull xM = f2sub(z0.r, z0.i);
            ull y0 = f2mul(x0, pk2(gk[0].x, gk[0].x));
            ull yM = f2mul(xM, pk2(gm[0].x, gm[0].x));
            S[0].r = f2mul(f2add(y0, yM), half);
            S[0].i = f2mul(f2sub(y0, yM), nhalf);
            c2 t; t.r = y[8].r; t.i = f2neg(y[8].i);     // Z[2048] = own y[8]
            stc(X, PD(2048), c2mulw(t, g2048));
        } else {
            c2 zk = y[0], zm = sb[0];
            c2 xe, xo;
            xe.r = f2mul(f2add(zk.r, zm.r), half);
            xe.i = f2mul(f2sub(zk.i, zm.i), half);
            xo.r = f2mul(f2add(zk.i, zm.i), half);
            xo.i = f2mul(f2sub(zk.r, zm.r), nhalf);
            float2 w = g_tw[k];
            c2 wxo = c2mulw(xo, w);
            c2 xf, xb;
            xf.r = f2add(xe.r, wxo.r); xf.i = f2add(xe.i, wxo.i);
            xb.r = f2sub(xe.r, wxo.r); xb.i = f2neg(f2sub(xe.i, wxo.i));
            c2 ya = c2mulw(xf, gk[0]);
            c2 yb = c2mulw(xb, gm[0]);
            c2 ye, dd;
            ye.r = f2mul(f2add(ya.r, yb.r), half);
            ye.i = f2mul(f2sub(ya.i, yb.i), half);
            dd.r = f2sub(ya.r, yb.r);
            dd.i = f2add(ya.i, yb.i);
            c2 yo = c2mulw(dd, make_float2(w.x, -w.y));
            yo.r = f2mul(yo.r, half); yo.i = f2mul(yo.i, half);
            S[0].r = f2sub(ye.r, yo.i);
            S[0].i = f2neg(f2add(ye.i, yo.r));
            c2 ob2;
            ob2.r = f2add(ye.r, yo.i);
            ob2.i = f2sub(ye.i, yo.r);
            stc(X, PD(4096 - k), ob2);
        }
    }
    // r = 1..7 branch-free (k = tid + 256r != 0 always)
#pragma unroll
    for (int r = 1; r < 8; r++) {
        int k = tid + (r << 8);
        ull half = pk2(0.5f, 0.5f), nhalf = pk2(-0.5f, -0.5f);
        c2 zk = y[r], zm = sb[r];
        c2 xe, xo;
        xe.r = f2mul(f2add(zk.r, zm.r), half);
        xe.i = f2mul(f2sub(zk.i, zm.i), half);
        xo.r = f2mul(f2add(zk.i, zm.i), half);
        xo.i = f2mul(f2sub(zk.r, zm.r), nhalf);
        float2 w = g_tw[k];
        c2 wxo = c2mulw(xo, w);
        c2 xf, xb;
        xf.r = f2add(xe.r, wxo.r); xf.i = f2add(xe.i, wxo.i);
        xb.r = f2sub(xe.r, wxo.r); xb.i = f2neg(f2sub(xe.i, wxo.i));
        c2 ya = c2mulw(xf, gk[r]);
        c2 yb = c2mulw(xb, gm[r]);
        c2 ye, dd;
        ye.r = f2mul(f2add(ya.r, yb.r), half);
        ye.i = f2mul(f2sub(ya.i, yb.i), half);
        dd.r = f2sub(ya.r, yb.r);
        dd.i = f2add(ya.i, yb.i);
        c2 yo = c2mulw(dd, make_float2(w.x, -w.y));
        yo.r = f2mul(yo.r, half); yo.i = f2mul(yo.i, half);
        S[r].r = f2sub(ye.r, yo.i);
        S[r].i = f2neg(f2add(ye.i, yo.r));
        c2 ob2;
        ob2.r = f2add(ye.r, yo.i);
        ob2.i = f2sub(ye.i, yo.r);
        stc(X, PD(4096 - k), ob2);
    }
    __syncthreads();

    // inverse FFT: stage0 mixed (lower from regs, upper from smem)
    fft_stage0_mixedP(X, tid, S);
    fft_stage1P(X, tid);
    {
        c2 x[16];
#pragma unroll
        for (int r = 0; r < 16; r++) x[r] = ldc(X, PD(tid + (r << 8)));
        c2 A0[4], A1[4], A2[4], A3[4];
        ALAYERP(x, A0, A1, A2, A3);
        c2 yf[8];
        BLAYER_UNIT_HALFP(A0, A1, A2, A3, yf);

        float dh = D[h];
        ull dh2 = pk2(dh, dh);
        ull inv2 = pk2(1.0f / Mh, 1.0f / Mh);
        ull ninv2 = pk2(-1.0f / Mh, -1.0f / Mh);
        float2* oA = (float2*)(out + rowA * Lq);
        float2* oB = (float2*)(out + rowB * Lq);
#pragma unroll
        for (int m = 0; m < 8; m++) {
            float2 a = uA[tid + (m << 8)], b = uB[tid + (m << 8)];   // L2 reload
            ull urr = pk2(a.x, b.x), uri = pk2(a.y, b.y);
            ull resr = f2fma(urr, dh2, f2mul(yf[m].r, inv2));
            ull resi = f2fma(uri, dh2, f2mul(yf[m].i, ninv2));
            float ra, rb, ia, ib;
            upk2(resr, ra, rb); upk2(resi, ia, ib);
            oA[tid + (m << 8)] = make_float2(ra, ia);
            oB[tid + (m << 8)] = make_float2(rb, ib);
        }
    }
}

// ---------------- launcher ----------------
extern "C" void kernel_launch(void* const* d_in, const int* in_sizes, int n_in,
                              void* d_out, int out_size) {
    const float* u  = (const float*)d_in[0];
    const float* W  = (const float*)d_in[1];
    const float* D  = (const float*)d_in[2];
    const float* ls = (const float*)d_in[3];
    const float* Lr = (const float*)d_in[4];
    const float* Li = (const float*)d_in[5];
    float* out = (float*)d_out;

    int fft_smem = PDN * (int)sizeof(u2);             // 69632 B
    int k_smem   = 8 * 2048 * (int)sizeof(float);     // 65536 B

    cudaFuncSetAttribute(k_kernel,    cudaFuncAttributeMaxDynamicSharedMemorySize, k_smem);
    cudaFuncSetAttribute(fftG_kernel, cudaFuncAttributeMaxDynamicSharedMemorySize, fft_smem);
    cudaFuncSetAttribute(conv_kernel, cudaFuncAttributeMaxDynamicSharedMemorySize, fft_smem);

    setup_kernel<<<16 + Hh, 256>>>(W, ls, Lr, Li);
    k_kernel<<<2 * Hh, 256, k_smem>>>();
    fftG_kernel<<<Hh / 2, 256, fft_smem>>>();
    conv_kernel<<<Bb * Hh / 2, 256, fft_smem>>>(u, D, out);
}